// round 15
// baseline (speedup 1.0000x reference)
#include <cuda_runtime.h>
#include <cuda_bf16.h>
#include <cstdint>

#define SEQ   4096
#define NBATCH 4
#define HD    64
#define DIN   1024
#define MTOT  (NBATCH * SEQ)

// Pre-split projected tensors (written by proj, read by attention)
__device__ __nv_bfloat16 g_Qhi[MTOT * HD], g_Qlo[MTOT * HD];
__device__ __nv_bfloat16 g_Khi[MTOT * HD], g_Klo[MTOT * HD];
__device__ __nv_bfloat16 g_VThi[NBATCH * HD * SEQ], g_VTlo[NBATCH * HD * SEQ];  // [b][dim][key]

// Pre-split W (smem image per (mat, chunk): 64 rows x 64 k, swizzled, 8KB each)
__device__ __nv_bfloat16 g_Wsphi[3 * 16 * 4096], g_Wsplo[3 * 16 * 4096];

__device__ __forceinline__ void split2(float a, float b, uint32_t& hi, uint32_t& lo) {
    __nv_bfloat162 h = __floats2bfloat162_rn(a, b);
    float ra = a - __bfloat162float(h.x);
    float rb = b - __bfloat162float(h.y);
    __nv_bfloat162 l = __floats2bfloat162_rn(ra, rb);
    hi = *(uint32_t*)&h;
    lo = *(uint32_t*)&l;
}

__device__ __forceinline__ void mma16816(float* c, const uint32_t* a, uint32_t b0, uint32_t b1) {
    asm volatile(
        "mma.sync.aligned.m16n8k16.row.col.f32.bf16.bf16.f32 "
        "{%0,%1,%2,%3}, {%4,%5,%6,%7}, {%8,%9}, {%0,%1,%2,%3};"
        : "+f"(c[0]), "+f"(c[1]), "+f"(c[2]), "+f"(c[3])
        : "r"(a[0]), "r"(a[1]), "r"(a[2]), "r"(a[3]), "r"(b0), "r"(b1));
}

__device__ __forceinline__ uint32_t smem_u32(const void* p) {
    uint32_t a;
    asm("{ .reg .u64 t; cvta.to.shared.u64 t, %1; cvt.u32.u64 %0, t; }" : "=r"(a) : "l"(p));
    return a;
}
#define CP_ASYNC16(dst, src) \
    asm volatile("cp.async.cg.shared.global [%0], [%1], 16;" :: "r"(dst), "l"(src) : "memory")
#define CP_COMMIT() asm volatile("cp.async.commit_group;" ::: "memory")
#define CP_WAIT0()  asm volatile("cp.async.wait_group 0;" ::: "memory")

// ===========================================================================
// W pre-split: 3 mats x 16 chunks x 4 quarters -> 192 CTAs
// ===========================================================================
__global__ void presplit_kernel(const float* __restrict__ Wq, const float* __restrict__ Wk,
                                const float* __restrict__ Wv)
{
    const int mat = blockIdx.x, c = blockIdx.y;
    const float* W = (mat == 0) ? Wq : (mat == 1) ? Wk : Wv;
    char* dhi = (char*)(g_Wsphi + (mat * 16 + c) * 4096);
    char* dlo = (char*)(g_Wsplo + (mat * 16 + c) * 4096);
    const int base = blockIdx.z * 1024;
    for (int i = base + threadIdx.x; i < base + 1024; i += 256) {
        int r = i >> 6, k = i & 63;
        float v = W[(size_t)r * DIN + c * 64 + k];
        __nv_bfloat16 h = __float2bfloat16(v);
        int off = r * 128 + (((k >> 3) ^ (r & 7)) << 4) + (k & 7) * 2;
        *(__nv_bfloat16*)(dhi + off) = h;
        *(__nv_bfloat16*)(dlo + off) = __float2bfloat16(v - __bfloat162float(h));
    }
}

// ===========================================================================
// Projection (unchanged): X via fp32 smem split in registers, W pre-split.
// ===========================================================================
#define XBUF(p) ((p) * 32768)
#define WBUF(p) (65536 + (p) * 16384)
#define PROJ_SMEM 98304

__global__ __launch_bounds__(256) void proj_mma_kernel(
    const float* __restrict__ q, const float* __restrict__ k, const float* __restrict__ v)
{
    extern __shared__ char sm[];
    const uint32_t sb = smem_u32(sm);
    const int mat = blockIdx.y;
    const float* __restrict__ x = (mat == 0) ? q : (mat == 1) ? k : v;

    const int t    = threadIdx.x;
    const int w    = t >> 5;
    const int lane = t & 31;
    const int grp  = lane >> 2;
    const int qd   = lane & 3;
    const int m0   = blockIdx.x * 128;
    const int r0   = w * 16 + grp;

    float acc[8][4];
#pragma unroll
    for (int nb = 0; nb < 8; nb++)
#pragma unroll
        for (int j = 0; j < 4; j++) acc[nb][j] = 0.f;

    const int xrow = t >> 4, xk4 = t & 15;

    auto issue_chunk = [&](int c, int p) {
#pragma unroll
        for (int u = 0; u < 8; ++u) {
            int row = xrow + 16 * u;
            uint32_t dst = sb + XBUF(p) + row * 256 + ((xk4 ^ (row & 7)) << 4);
            CP_ASYNC16(dst, x + (size_t)(m0 + row) * DIN + c * 64 + xk4 * 4);
        }
        const char* bh = (const char*)(g_Wsphi + (mat * 16 + c) * 4096);
        const char* bl = (const char*)(g_Wsplo + (mat * 16 + c) * 4096);
#pragma unroll
        for (int u = 0; u < 2; ++u) {
            int idx = t + 256 * u;
            CP_ASYNC16(sb + WBUF(p) + idx * 16, bh + idx * 16);
            CP_ASYNC16(sb + WBUF(p) + 8192 + idx * 16, bl + idx * 16);
        }
        CP_COMMIT();
    };

    issue_chunk(0, 0);

    for (int c = 0; c < 16; ++c) {
        const int p = c & 1;
        CP_WAIT0();
        __syncthreads();
        if (c < 15) issue_chunk(c + 1, p ^ 1);

        const char* xb = sm + XBUF(p);
        const char* wb = sm + WBUF(p);

#pragma unroll
        for (int ks = 0; ks < 4; ++ks) {
            const int k0 = 16 * ks + 2 * qd;
            const int k1 = k0 + 8;
            const int sw0 = (((k0 >> 2) ^ (r0 & 7)) << 4) + (k0 & 3) * 4;
            const int sw1 = (((k1 >> 2) ^ (r0 & 7)) << 4) + (k1 & 3) * 4;
            float2 f0 = *(const float2*)(xb + r0 * 256 + sw0);
            float2 f1 = *(const float2*)(xb + (r0 + 8) * 256 + sw0);
            float2 f2 = *(const float2*)(xb + r0 * 256 + sw1);
            float2 f3 = *(const float2*)(xb + (r0 + 8) * 256 + sw1);
            uint32_t ahi[4], alo[4];
            split2(f0.x, f0.y, ahi[0], alo[0]);
            split2(f1.x, f1.y, ahi[1], alo[1]);
            split2(f2.x, f2.y, ahi[2], alo[2]);
            split2(f3.x, f3.y, ahi[3], alo[3]);
#pragma unroll
            for (int nb = 0; nb < 8; ++nb) {
                const int row = nb * 8 + grp;
                const int sb0 = ((2 * ks) ^ (row & 7)) << 4;
                const int sb1 = ((2 * ks + 1) ^ (row & 7)) << 4;
                uint32_t bh0 = *(const uint32_t*)(wb + row * 128 + sb0 + 4 * qd);
                uint32_t bh1 = *(const uint32_t*)(wb + row * 128 + sb1 + 4 * qd);
                uint32_t bl0 = *(const uint32_t*)(wb + 8192 + row * 128 + sb0 + 4 * qd);
                uint32_t bl1 = *(const uint32_t*)(wb + 8192 + row * 128 + sb1 + 4 * qd);
                mma16816(acc[nb], ahi, bh0, bh1);
                mma16816(acc[nb], alo, bh0, bh1);
                mma16816(acc[nb], ahi, bl0, bl1);
            }
        }
    }

    const int row0 = m0 + r0;
    if (mat < 2) {
        __nv_bfloat16* ohi = (mat == 0) ? g_Qhi : g_Khi;
        __nv_bfloat16* olo = (mat == 0) ? g_Qlo : g_Klo;
#pragma unroll
        for (int nb = 0; nb < 8; ++nb) {
            const int col = nb * 8 + qd * 2;
            uint32_t h0, l0v, h1, l1v;
            split2(acc[nb][0], acc[nb][1], h0, l0v);
            split2(acc[nb][2], acc[nb][3], h1, l1v);
            *(uint32_t*)&ohi[(size_t)row0 * HD + col]       = h0;
            *(uint32_t*)&olo[(size_t)row0 * HD + col]       = l0v;
            *(uint32_t*)&ohi[(size_t)(row0 + 8) * HD + col] = h1;
            *(uint32_t*)&olo[(size_t)(row0 + 8) * HD + col] = l1v;
        }
    } else {
        const int batch = row0 >> 12;
        const int key   = row0 & 4095;
#pragma unroll
        for (int nb = 0; nb < 8; ++nb) {
            const int col = nb * 8 + qd * 2;
#pragma unroll
            for (int ci = 0; ci < 4; ++ci) {
                float val = acc[nb][ci];
                int cc = col + (ci & 1);
                int ky = key + ((ci >> 1) * 8);
                __nv_bfloat16 h = __float2bfloat16(val);
                size_t off = ((size_t)batch * HD + cc) * SEQ + ky;
                g_VThi[off] = h;
                g_VTlo[off] = __float2bfloat16(val - __bfloat162float(h));
            }
        }
    }
}

// ===========================================================================
// Flash attention: 256 threads, 4(M)x2(key-half) warps, ONE q-tile per CTA,
// 256 CTAs heavy-first (LPT), 2 CTAs/SM co-resident. Softmax-free (bounded
// scores), 2-buffer cp.async, 1 barrier/iter.
// ===========================================================================
#define SQHI 0
#define SQLO 8192
#define SBUF(p) (16384 + (p) * 32768)   // KHI | KLO | VHI | VLO, 8KB each
#define SREDS 81920                      // [2][64] float
#define SO0   16384                      // overlays SBUF(0) at epilogue
#define ATTN_SMEM 82944

__global__ __launch_bounds__(256, 2) void attn_mma_kernel(float* __restrict__ out)
{
    extern __shared__ char sm[];
    const uint32_t sbase = smem_u32(sm);
    float* sRedS = (float*)(sm + SREDS);

    // LPT: heavy q-tiles first. bid 0..255 -> qt 63..0, batch = bid & 3.
    const int bid = blockIdx.x;
    const int qt  = 63 - (bid >> 2);
    const int b   = bid & 3;

    const int t  = threadIdx.x;
    const int w  = t >> 5, lane = t & 31;
    const int wm = w & 3, wn = w >> 2;     // 4 M-warps x 2 key-halves
    const int grp = lane >> 2, qd = lane & 3;
    const int r0 = 16 * wm + grp;

    const __nv_bfloat16* Qh = g_Qhi + (size_t)b * SEQ * HD;
    const __nv_bfloat16* Ql = g_Qlo + (size_t)b * SEQ * HD;
    const __nv_bfloat16* Kh = g_Khi + (size_t)b * SEQ * HD;
    const __nv_bfloat16* Kl = g_Klo + (size_t)b * SEQ * HD;
    const __nv_bfloat16* Vh = g_VThi + (size_t)b * HD * SEQ;
    const __nv_bfloat16* Vl = g_VTlo + (size_t)b * HD * SEQ;

    // loader: 2 uint4 slots per 8KB array per thread
    int chA[4], chB[4];
#pragma unroll
    for (int ks = 0; ks < 4; ++ks) {
        chA[ks] = (((2 * ks) ^ grp) << 4) + qd * 4;
        chB[ks] = (((2 * ks + 1) ^ grp) << 4) + qd * 4;
    }

    // ---- issue Q + K/V tile 0
#pragma unroll
    for (int u = 0; u < 2; ++u) {
        const int idx = t + 256 * u;
        const int lrow = idx >> 3, lc4 = idx & 7;
        const uint32_t dof = (uint32_t)(lrow * 128 + ((lc4 ^ (lrow & 7)) << 4));
        CP_ASYNC16(sbase + SQHI + dof, Qh + (size_t)(qt * 64 + lrow) * HD + lc4 * 8);
        CP_ASYNC16(sbase + SQLO + dof, Ql + (size_t)(qt * 64 + lrow) * HD + lc4 * 8);
        CP_ASYNC16(sbase + SBUF(0) + dof,         Kh + (size_t)lrow * HD + lc4 * 8);
        CP_ASYNC16(sbase + SBUF(0) + 8192 + dof,  Kl + (size_t)lrow * HD + lc4 * 8);
        CP_ASYNC16(sbase + SBUF(0) + 16384 + dof, Vh + (size_t)lrow * SEQ + lc4 * 8);
        CP_ASYNC16(sbase + SBUF(0) + 24576 + dof, Vl + (size_t)lrow * SEQ + lc4 * 8);
    }
    CP_COMMIT();
    CP_WAIT0();
    __syncthreads();

    // ---- hoist Q hi fragments (lo read from smem per use)
    uint32_t qah[4][4];
#pragma unroll
    for (int ks = 0; ks < 4; ++ks) {
        qah[ks][0] = *(uint32_t*)(sm + SQHI + r0 * 128 + chA[ks]);
        qah[ks][1] = *(uint32_t*)(sm + SQHI + (r0 + 8) * 128 + chA[ks]);
        qah[ks][2] = *(uint32_t*)(sm + SQHI + r0 * 128 + chB[ks]);
        qah[ks][3] = *(uint32_t*)(sm + SQHI + (r0 + 8) * 128 + chB[ks]);
    }

    float o[8][4];
#pragma unroll
    for (int nb = 0; nb < 8; ++nb)
#pragma unroll
        for (int j = 0; j < 4; ++j) o[nb][j] = 0.f;
    float lp0 = 0.f, lp1 = 0.f;

    for (int kt = 0; kt <= qt; ++kt) {
        const int p = kt & 1;
        const char* bufp = sm + SBUF(p);

        // ---- prefetch tile kt+1 into alternate buffer
        if (kt < qt) {
            const uint32_t dst = sbase + SBUF(p ^ 1);
#pragma unroll
            for (int u = 0; u < 2; ++u) {
                const int idx = t + 256 * u;
                const int lrow = idx >> 3, lc4 = idx & 7;
                const uint32_t dof = (uint32_t)(lrow * 128 + ((lc4 ^ (lrow & 7)) << 4));
                CP_ASYNC16(dst + dof,         Kh + (size_t)((kt + 1) * 64 + lrow) * HD + lc4 * 8);
                CP_ASYNC16(dst + 8192 + dof,  Kl + (size_t)((kt + 1) * 64 + lrow) * HD + lc4 * 8);
                CP_ASYNC16(dst + 16384 + dof, Vh + (size_t)lrow * SEQ + (kt + 1) * 64 + lc4 * 8);
                CP_ASYNC16(dst + 24576 + dof, Vl + (size_t)lrow * SEQ + (kt + 1) * 64 + lc4 * 8);
            }
            CP_COMMIT();
        }

        // ---- S = Q K^T (16 rows x 32 keys per warp), split-3
        float s[4][4];
#pragma unroll
        for (int nb = 0; nb < 4; ++nb)
#pragma unroll
            for (int j = 0; j < 4; ++j) s[nb][j] = 0.f;

#pragma unroll
        for (int ks = 0; ks < 4; ++ks) {
            uint32_t al[4];
            al[0] = *(uint32_t*)(sm + SQLO + r0 * 128 + chA[ks]);
            al[1] = *(uint32_t*)(sm + SQLO + (r0 + 8) * 128 + chA[ks]);
            al[2] = *(uint32_t*)(sm + SQLO + r0 * 128 + chB[ks]);
            al[3] = *(uint32_t*)(sm + SQLO + (r0 + 8) * 128 + chB[ks]);
#pragma unroll
            for (int nb = 0; nb < 4; ++nb) {
                const int krow = wn * 32 + nb * 8 + grp;
                uint32_t bh0 = *(uint32_t*)(bufp + krow * 128 + chA[ks]);
                uint32_t bh1 = *(uint32_t*)(bufp + krow * 128 + chB[ks]);
                uint32_t bl0 = *(uint32_t*)(bufp + 8192 + krow * 128 + chA[ks]);
                uint32_t bl1 = *(uint32_t*)(bufp + 8192 + krow * 128 + chB[ks]);
                mma16816(s[nb], qah[ks], bh0, bh1);
                mma16816(s[nb], al, bh0, bh1);
                mma16816(s[nb], qah[ks], bl0, bl1);
            }
        }

        // ---- softmax numerator (no max shift: scores bounded)
        const float sc = 0.125f;
        if (kt == qt) {
#pragma unroll
            for (int nb = 0; nb < 4; ++nb) {
                const int colb = wn * 32 + nb * 8 + 2 * qd;
                s[nb][0] = (colb     > r0)     ? 0.f : __expf(s[nb][0] * sc);
                s[nb][1] = (colb + 1 > r0)     ? 0.f : __expf(s[nb][1] * sc);
                s[nb][2] = (colb     > r0 + 8) ? 0.f : __expf(s[nb][2] * sc);
                s[nb][3] = (colb + 1 > r0 + 8) ? 0.f : __expf(s[nb][3] * sc);
            }
        } else {
#pragma unroll
            for (int nb = 0; nb < 4; ++nb)
#pragma unroll
                for (int j = 0; j < 4; ++j) s[nb][j] = __expf(s[nb][j] * sc);
        }
#pragma unroll
        for (int nb = 0; nb < 4; ++nb) {
            lp0 += s[nb][0] + s[nb][1];
            lp1 += s[nb][2] + s[nb][3];
        }

        // ---- P -> A-fragments (registers only)
        uint32_t ph[2][4], pl[2][4];
#pragma unroll
        for (int j = 0; j < 2; ++j) {
            split2(s[2 * j][0],     s[2 * j][1],     ph[j][0], pl[j][0]);
            split2(s[2 * j][2],     s[2 * j][3],     ph[j][1], pl[j][1]);
            split2(s[2 * j + 1][0], s[2 * j + 1][1], ph[j][2], pl[j][2]);
            split2(s[2 * j + 1][2], s[2 * j + 1][3], ph[j][3], pl[j][3]);
        }

        // ---- O += P V over this warp's 32 keys, split-3
#pragma unroll
        for (int j = 0; j < 2; ++j) {
            const int cb0 = (((4 * wn + 2 * j) ^ grp) << 4) + qd * 4;
            const int cb1 = (((4 * wn + 2 * j + 1) ^ grp) << 4) + qd * 4;
#pragma unroll
            for (int nb = 0; nb < 8; ++nb) {
                const int vrow = nb * 8 + grp;
                uint32_t vh0 = *(uint32_t*)(bufp + 16384 + vrow * 128 + cb0);
                uint32_t vh1 = *(uint32_t*)(bufp + 16384 + vrow * 128 + cb1);
                uint32_t vl0 = *(uint32_t*)(bufp + 24576 + vrow * 128 + cb0);
                uint32_t vl1 = *(uint32_t*)(bufp + 24576 + vrow * 128 + cb1);
                mma16816(o[nb], ph[j], vh0, vh1);
                mma16816(o[nb], pl[j], vh0, vh1);
                mma16816(o[nb], ph[j], vl0, vl1);
            }
        }

        if (kt < qt) CP_WAIT0();
        __syncthreads();   // buffer p consumed; buffer p^1 visible
    }  // kt

    // ---- l reduction (once per q-tile)
    lp0 += __shfl_xor_sync(0xffffffffu, lp0, 1);
    lp0 += __shfl_xor_sync(0xffffffffu, lp0, 2);
    lp1 += __shfl_xor_sync(0xffffffffu, lp1, 1);
    lp1 += __shfl_xor_sync(0xffffffffu, lp1, 2);
    if (qd == 0) { sRedS[wn * 64 + r0] = lp0; sRedS[wn * 64 + r0 + 8] = lp1; }
    __syncthreads();
    const float l0 = sRedS[r0] + sRedS[64 + r0];
    const float l1 = sRedS[r0 + 8] + sRedS[64 + r0 + 8];

    // ---- merge the two key-half partials, normalize, write
    float* sO0 = (float*)(sm + SO0);
    if (wn == 0) {
#pragma unroll
        for (int nb = 0; nb < 8; ++nb) {
            const int col = nb * 8 + 2 * qd;
            *(float2*)&sO0[r0 * 66 + col]       = make_float2(o[nb][0], o[nb][1]);
            *(float2*)&sO0[(r0 + 8) * 66 + col] = make_float2(o[nb][2], o[nb][3]);
        }
    }
    __syncthreads();
    if (wn == 1) {
        const float i0 = 1.f / l0, i1 = 1.f / l1;
        float* orow0 = out + ((size_t)b * SEQ + qt * 64 + r0) * HD;
        float* orow1 = orow0 + 8 * HD;
#pragma unroll
        for (int nb = 0; nb < 8; ++nb) {
            const int col = nb * 8 + 2 * qd;
            float2 p0 = *(float2*)&sO0[r0 * 66 + col];
            float2 p1 = *(float2*)&sO0[(r0 + 8) * 66 + col];
            *(float2*)&orow0[col] = make_float2((p0.x + o[nb][0]) * i0, (p0.y + o[nb][1]) * i0);
            *(float2*)&orow1[col] = make_float2((p1.x + o[nb][2]) * i1, (p1.y + o[nb][3]) * i1);
        }
    }
}

// ---------------------------------------------------------------------------
extern "C" void kernel_launch(void* const* d_in, const int* in_sizes, int n_in,
                              void* d_out, int out_size)
{
    const float* q  = (const float*)d_in[0];
    const float* k  = (const float*)d_in[1];
    const float* v  = (const float*)d_in[2];
    const float* Wq = (const float*)d_in[3];
    const float* Wk = (const float*)d_in[4];
    const float* Wv = (const float*)d_in[5];
    float* out = (float*)d_out;

    cudaFuncSetAttribute(proj_mma_kernel, cudaFuncAttributeMaxDynamicSharedMemorySize, PROJ_SMEM);
    cudaFuncSetAttribute(attn_mma_kernel, cudaFuncAttributeMaxDynamicSharedMemorySize, ATTN_SMEM);

    dim3 wgrid(3, 16, 4);
    presplit_kernel<<<wgrid, 256>>>(Wq, Wk, Wv);

    dim3 pgrid(128, 3);
    proj_mma_kernel<<<pgrid, 256, PROJ_SMEM>>>(q, k, v);

    attn_mma_kernel<<<256, 256, ATTN_SMEM>>>(out);
}

// round 16
// speedup vs baseline: 1.0754x; 1.0754x over previous
#include <cuda_runtime.h>
#include <cuda_bf16.h>
#include <cstdint>

#define SEQ   4096
#define NBATCH 4
#define HD    64
#define DIN   1024
#define MTOT  (NBATCH * SEQ)

// Pre-split projected tensors (written by proj, read by attention)
__device__ __nv_bfloat16 g_Qhi[MTOT * HD], g_Qlo[MTOT * HD];
__device__ __nv_bfloat16 g_Khi[MTOT * HD], g_Klo[MTOT * HD];
__device__ __nv_bfloat16 g_VThi[NBATCH * HD * SEQ], g_VTlo[NBATCH * HD * SEQ];  // [b][dim][key]

// Pre-split W (smem image per (mat, chunk): 64 rows x 64 k, swizzled, 8KB each)
__device__ __nv_bfloat16 g_Wsphi[3 * 16 * 4096], g_Wsplo[3 * 16 * 4096];

// Dynamic work queue for persistent attention CTAs
__device__ int g_work;

__device__ __forceinline__ void split2(float a, float b, uint32_t& hi, uint32_t& lo) {
    __nv_bfloat162 h = __floats2bfloat162_rn(a, b);
    float ra = a - __bfloat162float(h.x);
    float rb = b - __bfloat162float(h.y);
    __nv_bfloat162 l = __floats2bfloat162_rn(ra, rb);
    hi = *(uint32_t*)&h;
    lo = *(uint32_t*)&l;
}

__device__ __forceinline__ void mma16816(float* c, const uint32_t* a, uint32_t b0, uint32_t b1) {
    asm volatile(
        "mma.sync.aligned.m16n8k16.row.col.f32.bf16.bf16.f32 "
        "{%0,%1,%2,%3}, {%4,%5,%6,%7}, {%8,%9}, {%0,%1,%2,%3};"
        : "+f"(c[0]), "+f"(c[1]), "+f"(c[2]), "+f"(c[3])
        : "r"(a[0]), "r"(a[1]), "r"(a[2]), "r"(a[3]), "r"(b0), "r"(b1));
}

__device__ __forceinline__ uint32_t smem_u32(const void* p) {
    uint32_t a;
    asm("{ .reg .u64 t; cvta.to.shared.u64 t, %1; cvt.u32.u64 %0, t; }" : "=r"(a) : "l"(p));
    return a;
}
#define CP_ASYNC16(dst, src) \
    asm volatile("cp.async.cg.shared.global [%0], [%1], 16;" :: "r"(dst), "l"(src) : "memory")
#define CP_COMMIT() asm volatile("cp.async.commit_group;" ::: "memory")
#define CP_WAIT0()  asm volatile("cp.async.wait_group 0;" ::: "memory")

// ===========================================================================
// W pre-split (also resets the attention work queue each launch)
// ===========================================================================
__global__ void presplit_kernel(const float* __restrict__ Wq, const float* __restrict__ Wk,
                                const float* __restrict__ Wv)
{
    if (threadIdx.x == 0 && blockIdx.x == 0 && blockIdx.y == 0 && blockIdx.z == 0)
        g_work = 0;
    const int mat = blockIdx.x, c = blockIdx.y;
    const float* W = (mat == 0) ? Wq : (mat == 1) ? Wk : Wv;
    char* dhi = (char*)(g_Wsphi + (mat * 16 + c) * 4096);
    char* dlo = (char*)(g_Wsplo + (mat * 16 + c) * 4096);
    const int base = blockIdx.z * 1024;
    for (int i = base + threadIdx.x; i < base + 1024; i += 256) {
        int r = i >> 6, k = i & 63;
        float v = W[(size_t)r * DIN + c * 64 + k];
        __nv_bfloat16 h = __float2bfloat16(v);
        int off = r * 128 + (((k >> 3) ^ (r & 7)) << 4) + (k & 7) * 2;
        *(__nv_bfloat16*)(dhi + off) = h;
        *(__nv_bfloat16*)(dlo + off) = __float2bfloat16(v - __bfloat162float(h));
    }
}

// ===========================================================================
// Projection (unchanged): X via fp32 smem split in registers, W pre-split.
// ===========================================================================
#define XBUF(p) ((p) * 32768)
#define WBUF(p) (65536 + (p) * 16384)
#define PROJ_SMEM 98304

__global__ __launch_bounds__(256) void proj_mma_kernel(
    const float* __restrict__ q, const float* __restrict__ k, const float* __restrict__ v)
{
    extern __shared__ char sm[];
    const uint32_t sb = smem_u32(sm);
    const int mat = blockIdx.y;
    const float* __restrict__ x = (mat == 0) ? q : (mat == 1) ? k : v;

    const int t    = threadIdx.x;
    const int w    = t >> 5;
    const int lane = t & 31;
    const int grp  = lane >> 2;
    const int qd   = lane & 3;
    const int m0   = blockIdx.x * 128;
    const int r0   = w * 16 + grp;

    float acc[8][4];
#pragma unroll
    for (int nb = 0; nb < 8; nb++)
#pragma unroll
        for (int j = 0; j < 4; j++) acc[nb][j] = 0.f;

    const int xrow = t >> 4, xk4 = t & 15;

    auto issue_chunk = [&](int c, int p) {
#pragma unroll
        for (int u = 0; u < 8; ++u) {
            int row = xrow + 16 * u;
            uint32_t dst = sb + XBUF(p) + row * 256 + ((xk4 ^ (row & 7)) << 4);
            CP_ASYNC16(dst, x + (size_t)(m0 + row) * DIN + c * 64 + xk4 * 4);
        }
        const char* bh = (const char*)(g_Wsphi + (mat * 16 + c) * 4096);
        const char* bl = (const char*)(g_Wsplo + (mat * 16 + c) * 4096);
#pragma unroll
        for (int u = 0; u < 2; ++u) {
            int idx = t + 256 * u;
            CP_ASYNC16(sb + WBUF(p) + idx * 16, bh + idx * 16);
            CP_ASYNC16(sb + WBUF(p) + 8192 + idx * 16, bl + idx * 16);
        }
        CP_COMMIT();
    };

    issue_chunk(0, 0);

    for (int c = 0; c < 16; ++c) {
        const int p = c & 1;
        CP_WAIT0();
        __syncthreads();
        if (c < 15) issue_chunk(c + 1, p ^ 1);

        const char* xb = sm + XBUF(p);
        const char* wb = sm + WBUF(p);

#pragma unroll
        for (int ks = 0; ks < 4; ++ks) {
            const int k0 = 16 * ks + 2 * qd;
            const int k1 = k0 + 8;
            const int sw0 = (((k0 >> 2) ^ (r0 & 7)) << 4) + (k0 & 3) * 4;
            const int sw1 = (((k1 >> 2) ^ (r0 & 7)) << 4) + (k1 & 3) * 4;
            float2 f0 = *(const float2*)(xb + r0 * 256 + sw0);
            float2 f1 = *(const float2*)(xb + (r0 + 8) * 256 + sw0);
            float2 f2 = *(const float2*)(xb + r0 * 256 + sw1);
            float2 f3 = *(const float2*)(xb + (r0 + 8) * 256 + sw1);
            uint32_t ahi[4], alo[4];
            split2(f0.x, f0.y, ahi[0], alo[0]);
            split2(f1.x, f1.y, ahi[1], alo[1]);
            split2(f2.x, f2.y, ahi[2], alo[2]);
            split2(f3.x, f3.y, ahi[3], alo[3]);
#pragma unroll
            for (int nb = 0; nb < 8; ++nb) {
                const int row = nb * 8 + grp;
                const int sb0 = ((2 * ks) ^ (row & 7)) << 4;
                const int sb1 = ((2 * ks + 1) ^ (row & 7)) << 4;
                uint32_t bh0 = *(const uint32_t*)(wb + row * 128 + sb0 + 4 * qd);
                uint32_t bh1 = *(const uint32_t*)(wb + row * 128 + sb1 + 4 * qd);
                uint32_t bl0 = *(const uint32_t*)(wb + 8192 + row * 128 + sb0 + 4 * qd);
                uint32_t bl1 = *(const uint32_t*)(wb + 8192 + row * 128 + sb1 + 4 * qd);
                mma16816(acc[nb], ahi, bh0, bh1);
                mma16816(acc[nb], alo, bh0, bh1);
                mma16816(acc[nb], ahi, bl0, bl1);
            }
        }
    }

    const int row0 = m0 + r0;
    if (mat < 2) {
        __nv_bfloat16* ohi = (mat == 0) ? g_Qhi : g_Khi;
        __nv_bfloat16* olo = (mat == 0) ? g_Qlo : g_Klo;
#pragma unroll
        for (int nb = 0; nb < 8; ++nb) {
            const int col = nb * 8 + qd * 2;
            uint32_t h0, l0v, h1, l1v;
            split2(acc[nb][0], acc[nb][1], h0, l0v);
            split2(acc[nb][2], acc[nb][3], h1, l1v);
            *(uint32_t*)&ohi[(size_t)row0 * HD + col]       = h0;
            *(uint32_t*)&olo[(size_t)row0 * HD + col]       = l0v;
            *(uint32_t*)&ohi[(size_t)(row0 + 8) * HD + col] = h1;
            *(uint32_t*)&olo[(size_t)(row0 + 8) * HD + col] = l1v;
        }
    } else {
        const int batch = row0 >> 12;
        const int key   = row0 & 4095;
#pragma unroll
        for (int nb = 0; nb < 8; ++nb) {
            const int col = nb * 8 + qd * 2;
#pragma unroll
            for (int ci = 0; ci < 4; ++ci) {
                float val = acc[nb][ci];
                int cc = col + (ci & 1);
                int ky = key + ((ci >> 1) * 8);
                __nv_bfloat16 h = __float2bfloat16(val);
                size_t off = ((size_t)batch * HD + cc) * SEQ + ky;
                g_VThi[off] = h;
                g_VTlo[off] = __float2bfloat16(val - __bfloat162float(h));
            }
        }
    }
}

// ===========================================================================
// Flash attention: persistent 512-thread CTAs (grid=148), dynamic heavy-first
// work queue over 256 q-tiles. Inner loop identical to the 166.4us R11 kernel:
// 4(M)x4(key-quarter) warps, 2-buffer cp.async, softmax-free, 1 barrier/iter.
// ===========================================================================
#define SQHI 0
#define SQLO 8192
#define SBUF(p) (16384 + (p) * 32768)   // KHI | KLO | VHI | VLO, 8KB each
#define SREDS 81920                      // [4][64] float
#define SO0   16384
#define SO1   33792
#define SJOB  82944
#define ATTN_SMEM 82960

__global__ __launch_bounds__(512) void attn_mma_kernel(float* __restrict__ out)
{
    extern __shared__ char sm[];
    const uint32_t sbase = smem_u32(sm);
    float* sRedS = (float*)(sm + SREDS);
    int* sJob = (int*)(sm + SJOB);

    const int t  = threadIdx.x;
    const int w  = t >> 5, lane = t & 31;
    const int wm = w & 3, wn = w >> 2;
    const int grp = lane >> 2, qd = lane & 3;
    const int r0 = 16 * wm + grp;

    const int lrow = t >> 3, lc4 = t & 7;
    const uint32_t ldof = (uint32_t)(lrow * 128 + ((lc4 ^ (lrow & 7)) << 4));

    int chA[4], chB[4];
#pragma unroll
    for (int ks = 0; ks < 4; ++ks) {
        chA[ks] = (((2 * ks) ^ grp) << 4) + qd * 4;
        chB[ks] = (((2 * ks + 1) ^ grp) << 4) + qd * 4;
    }

    while (true) {
        if (t == 0) *sJob = atomicAdd(&g_work, 1);
        __syncthreads();
        const int job = *sJob;
        if (job >= 256) break;
        // heavy-first: job 0..255 -> qt 63..0, batch = job & 3
        const int qt = 63 - (job >> 2);
        const int b  = job & 3;

        const __nv_bfloat16* Qh = g_Qhi + (size_t)b * SEQ * HD;
        const __nv_bfloat16* Ql = g_Qlo + (size_t)b * SEQ * HD;
        const __nv_bfloat16* Kh = g_Khi + (size_t)b * SEQ * HD;
        const __nv_bfloat16* Kl = g_Klo + (size_t)b * SEQ * HD;
        const __nv_bfloat16* Vh = g_VThi + (size_t)b * HD * SEQ;
        const __nv_bfloat16* Vl = g_VTlo + (size_t)b * HD * SEQ;

        // ---- issue Q + K/V tile 0
        CP_ASYNC16(sbase + SQHI + ldof, Qh + (size_t)(qt * 64 + lrow) * HD + lc4 * 8);
        CP_ASYNC16(sbase + SQLO + ldof, Ql + (size_t)(qt * 64 + lrow) * HD + lc4 * 8);
        CP_ASYNC16(sbase + SBUF(0) + ldof,         Kh + (size_t)lrow * HD + lc4 * 8);
        CP_ASYNC16(sbase + SBUF(0) + 8192 + ldof,  Kl + (size_t)lrow * HD + lc4 * 8);
        CP_ASYNC16(sbase + SBUF(0) + 16384 + ldof, Vh + (size_t)lrow * SEQ + lc4 * 8);
        CP_ASYNC16(sbase + SBUF(0) + 24576 + ldof, Vl + (size_t)lrow * SEQ + lc4 * 8);
        CP_COMMIT();
        CP_WAIT0();
        __syncthreads();

        // ---- hoist Q hi fragments (lo read from smem per use)
        uint32_t qah[4][4];
#pragma unroll
        for (int ks = 0; ks < 4; ++ks) {
            qah[ks][0] = *(uint32_t*)(sm + SQHI + r0 * 128 + chA[ks]);
            qah[ks][1] = *(uint32_t*)(sm + SQHI + (r0 + 8) * 128 + chA[ks]);
            qah[ks][2] = *(uint32_t*)(sm + SQHI + r0 * 128 + chB[ks]);
            qah[ks][3] = *(uint32_t*)(sm + SQHI + (r0 + 8) * 128 + chB[ks]);
        }

        float o[8][4];
#pragma unroll
        for (int nb = 0; nb < 8; ++nb)
#pragma unroll
            for (int j = 0; j < 4; ++j) o[nb][j] = 0.f;
        float lp0 = 0.f, lp1 = 0.f;

        for (int kt = 0; kt <= qt; ++kt) {
            const int p = kt & 1;
            const char* bufp = sm + SBUF(p);

            if (kt < qt) {
                const uint32_t dst = sbase + SBUF(p ^ 1);
                CP_ASYNC16(dst + ldof,         Kh + (size_t)((kt + 1) * 64 + lrow) * HD + lc4 * 8);
                CP_ASYNC16(dst + 8192 + ldof,  Kl + (size_t)((kt + 1) * 64 + lrow) * HD + lc4 * 8);
                CP_ASYNC16(dst + 16384 + ldof, Vh + (size_t)lrow * SEQ + (kt + 1) * 64 + lc4 * 8);
                CP_ASYNC16(dst + 24576 + ldof, Vl + (size_t)lrow * SEQ + (kt + 1) * 64 + lc4 * 8);
                CP_COMMIT();
            }

            // ---- S = Q K^T (16 rows x 16 keys per warp), split-3
            float s[2][4];
#pragma unroll
            for (int nb = 0; nb < 2; ++nb)
#pragma unroll
                for (int j = 0; j < 4; ++j) s[nb][j] = 0.f;

#pragma unroll
            for (int ks = 0; ks < 4; ++ks) {
                uint32_t al[4];
                al[0] = *(uint32_t*)(sm + SQLO + r0 * 128 + chA[ks]);
                al[1] = *(uint32_t*)(sm + SQLO + (r0 + 8) * 128 + chA[ks]);
                al[2] = *(uint32_t*)(sm + SQLO + r0 * 128 + chB[ks]);
                al[3] = *(uint32_t*)(sm + SQLO + (r0 + 8) * 128 + chB[ks]);
#pragma unroll
                for (int nb = 0; nb < 2; ++nb) {
                    const int krow = wn * 16 + nb * 8 + grp;
                    uint32_t bh0 = *(uint32_t*)(bufp + krow * 128 + chA[ks]);
                    uint32_t bh1 = *(uint32_t*)(bufp + krow * 128 + chB[ks]);
                    uint32_t bl0 = *(uint32_t*)(bufp + 8192 + krow * 128 + chA[ks]);
                    uint32_t bl1 = *(uint32_t*)(bufp + 8192 + krow * 128 + chB[ks]);
                    mma16816(s[nb], qah[ks], bh0, bh1);
                    mma16816(s[nb], al, bh0, bh1);
                    mma16816(s[nb], qah[ks], bl0, bl1);
                }
            }

            // ---- softmax numerator (no max shift: scores bounded)
            const float sc = 0.125f;
            if (kt == qt) {
#pragma unroll
                for (int nb = 0; nb < 2; ++nb) {
                    const int colb = wn * 16 + nb * 8 + 2 * qd;
                    s[nb][0] = (colb     > r0)     ? 0.f : __expf(s[nb][0] * sc);
                    s[nb][1] = (colb + 1 > r0)     ? 0.f : __expf(s[nb][1] * sc);
                    s[nb][2] = (colb     > r0 + 8) ? 0.f : __expf(s[nb][2] * sc);
                    s[nb][3] = (colb + 1 > r0 + 8) ? 0.f : __expf(s[nb][3] * sc);
                }
            } else {
#pragma unroll
                for (int nb = 0; nb < 2; ++nb)
#pragma unroll
                    for (int j = 0; j < 4; ++j) s[nb][j] = __expf(s[nb][j] * sc);
            }
            lp0 += s[0][0] + s[0][1] + s[1][0] + s[1][1];
            lp1 += s[0][2] + s[0][3] + s[1][2] + s[1][3];

            // ---- P -> A-fragments (registers only)
            uint32_t ph[4], pl[4];
            split2(s[0][0], s[0][1], ph[0], pl[0]);
            split2(s[0][2], s[0][3], ph[1], pl[1]);
            split2(s[1][0], s[1][1], ph[2], pl[2]);
            split2(s[1][2], s[1][3], ph[3], pl[3]);

            // ---- O += P V over this warp's 16 keys, split-3
            const int cb0 = (((2 * wn) ^ grp) << 4) + qd * 4;
            const int cb1 = (((2 * wn + 1) ^ grp) << 4) + qd * 4;
#pragma unroll
            for (int nb = 0; nb < 8; ++nb) {
                const int vrow = nb * 8 + grp;
                uint32_t vh0 = *(uint32_t*)(bufp + 16384 + vrow * 128 + cb0);
                uint32_t vh1 = *(uint32_t*)(bufp + 16384 + vrow * 128 + cb1);
                uint32_t vl0 = *(uint32_t*)(bufp + 24576 + vrow * 128 + cb0);
                uint32_t vl1 = *(uint32_t*)(bufp + 24576 + vrow * 128 + cb1);
                mma16816(o[nb], ph, vh0, vh1);
                mma16816(o[nb], pl, vh0, vh1);
                mma16816(o[nb], ph, vl0, vl1);
            }

            if (kt < qt) CP_WAIT0();
            __syncthreads();   // buffer p consumed; buffer p^1 visible
        }  // kt

        // ---- l reduction (once per q-tile)
        lp0 += __shfl_xor_sync(0xffffffffu, lp0, 1);
        lp0 += __shfl_xor_sync(0xffffffffu, lp0, 2);
        lp1 += __shfl_xor_sync(0xffffffffu, lp1, 1);
        lp1 += __shfl_xor_sync(0xffffffffu, lp1, 2);
        if (qd == 0) { sRedS[wn * 64 + r0] = lp0; sRedS[wn * 64 + r0 + 8] = lp1; }
        __syncthreads();
        const float l0 = sRedS[r0] + sRedS[64 + r0] + sRedS[128 + r0] + sRedS[192 + r0];
        const float l1 = sRedS[r0 + 8] + sRedS[64 + r0 + 8]
                       + sRedS[128 + r0 + 8] + sRedS[192 + r0 + 8];

        // ---- merge 4 key-quarter partials, normalize, write
        float* sO0 = (float*)(sm + SO0);
        float* sO1 = (float*)(sm + SO1);
        if (wn == 0 || wn == 2) {
            float* d = (wn == 0) ? sO0 : sO1;
#pragma unroll
            for (int nb = 0; nb < 8; ++nb) {
                const int col = nb * 8 + 2 * qd;
                *(float2*)&d[r0 * 66 + col]       = make_float2(o[nb][0], o[nb][1]);
                *(float2*)&d[(r0 + 8) * 66 + col] = make_float2(o[nb][2], o[nb][3]);
            }
        }
        __syncthreads();
        if (wn == 1) {
#pragma unroll
            for (int nb = 0; nb < 8; ++nb) {
                const int col = nb * 8 + 2 * qd;
                float2 p0 = *(float2*)&sO0[r0 * 66 + col];
                float2 p1 = *(float2*)&sO0[(r0 + 8) * 66 + col];
                *(float2*)&sO0[r0 * 66 + col]       = make_float2(p0.x + o[nb][0], p0.y + o[nb][1]);
                *(float2*)&sO0[(r0 + 8) * 66 + col] = make_float2(p1.x + o[nb][2], p1.y + o[nb][3]);
            }
        }
        if (wn == 3) {
#pragma unroll
            for (int nb = 0; nb < 8; ++nb) {
                const int col = nb * 8 + 2 * qd;
                float2 p0 = *(float2*)&sO1[r0 * 66 + col];
                float2 p1 = *(float2*)&sO1[(r0 + 8) * 66 + col];
                o[nb][0] += p0.x; o[nb][1] += p0.y;
                o[nb][2] += p1.x; o[nb][3] += p1.y;
            }
        }
        __syncthreads();
        if (wn == 3) {
            const float i0 = 1.f / l0, i1 = 1.f / l1;
            float* orow0 = out + ((size_t)b * SEQ + qt * 64 + r0) * HD;
            float* orow1 = orow0 + 8 * HD;
#pragma unroll
            for (int nb = 0; nb < 8; ++nb) {
                const int col = nb * 8 + 2 * qd;
                float2 p0 = *(float2*)&sO0[r0 * 66 + col];
                float2 p1 = *(float2*)&sO0[(r0 + 8) * 66 + col];
                *(float2*)&orow0[col] = make_float2((p0.x + o[nb][0]) * i0, (p0.y + o[nb][1]) * i0);
                *(float2*)&orow1[col] = make_float2((p1.x + o[nb][2]) * i1, (p1.y + o[nb][3]) * i1);
            }
        }
        __syncthreads();  // smem (incl. sJob) free before next job
    }  // job loop
}

// ---------------------------------------------------------------------------
extern "C" void kernel_launch(void* const* d_in, const int* in_sizes, int n_in,
                              void* d_out, int out_size)
{
    const float* q  = (const float*)d_in[0];
    const float* k  = (const float*)d_in[1];
    const float* v  = (const float*)d_in[2];
    const float* Wq = (const float*)d_in[3];
    const float* Wk = (const float*)d_in[4];
    const float* Wv = (const float*)d_in[5];
    float* out = (float*)d_out;

    cudaFuncSetAttribute(proj_mma_kernel, cudaFuncAttributeMaxDynamicSharedMemorySize, PROJ_SMEM);
    cudaFuncSetAttribute(attn_mma_kernel, cudaFuncAttributeMaxDynamicSharedMemorySize, ATTN_SMEM);

    dim3 wgrid(3, 16, 4);
    presplit_kernel<<<wgrid, 256>>>(Wq, Wk, Wv);

    dim3 pgrid(128, 3);
    proj_mma_kernel<<<pgrid, 256, PROJ_SMEM>>>(q, k, v);

    attn_mma_kernel<<<148, 512, ATTN_SMEM>>>(out);
}